// round 4
// baseline (speedup 1.0000x reference)
#include <cuda_runtime.h>
#include <cuda_fp16.h>
#include <math.h>

#define Bc   4
#define C    48
#define C3   144
#define HH   256
#define WW   256
#define NPIX 65536   // HH*WW

typedef unsigned long long u64;

// packed f32x2 helpers (sm_100+: fma.rn.f32x2 = 2 fp32 FMAs / instruction)
__device__ __forceinline__ void ffma2(u64& d, u64 a, u64 b, u64 c) {
    asm("fma.rn.f32x2 %0, %1, %2, %3;" : "=l"(d) : "l"(a), "l"(b), "l"(c));
}
__device__ __forceinline__ u64 pack2(float x, float y) {
    u64 r; asm("mov.b64 %0, {%1, %2};" : "=l"(r) : "f"(x), "f"(y)); return r;
}
__device__ __forceinline__ void unpack2(float& x, float& y, u64 v) {
    asm("mov.b64 {%0, %1}, %2;" : "=f"(x), "=f"(y) : "l"(v));
}

// ---- scratch (device globals: no allocation allowed) ----
__device__ __half g_qkv[(size_t)Bc * C3 * NPIX];   // after 1x1 conv (75 MB)
__device__ __half g_dw [(size_t)Bc * C3 * NPIX];   // after depthwise (75 MB)
__device__ float  g_small[Bc * (C * C + 2 * C)];   // gram | qss | kss

// ============================================================
// K1: qkv 1x1 conv. Accumulators packed over (oc,oc+1) pairs:
// w-pairs are native u64 broadcasts from k-major smem; x duplicated
// once per k into registers and reused across all 72 oc-pairs.
// 1 px/thread, 256 threads, 2 blocks/SM.
// ============================================================
__global__ __launch_bounds__(256, 2) void k_qkv(const float* __restrict__ x,
                                                const float* __restrict__ w) {
    __shared__ float wT[C][C3];  // wT[k][oc], 27.6 KB
    const int tid = threadIdx.x;
    for (int i = tid; i < C3 * C; i += 256) wT[i % C][i / C] = w[i];
    __syncthreads();

    const int b  = blockIdx.x >> 8;                 // 256 blocks / batch
    const int px = ((blockIdx.x & 255) << 8) | tid;

    const float* xb = x + (size_t)b * C * NPIX + px;
    u64 xd[C];
#pragma unroll
    for (int ic = 0; ic < C; ic++) { float v = xb[(size_t)ic * NPIX]; xd[ic] = pack2(v, v); }

    __half* ob = g_qkv + (size_t)b * C3 * NPIX + px;
    for (int ch = 0; ch < 9; ch++) {               // 16 oc per chunk
        u64 acc0 = 0, acc1 = 0, acc2 = 0, acc3 = 0, acc4 = 0, acc5 = 0, acc6 = 0, acc7 = 0;
#pragma unroll
        for (int k = 0; k < C; k++) {
            const ulonglong2* w2 = (const ulonglong2*)&wT[k][ch * 16];
            ulonglong2 p0 = w2[0], p1 = w2[1], p2 = w2[2], p3 = w2[3];
            ffma2(acc0, p0.x, xd[k], acc0);
            ffma2(acc1, p0.y, xd[k], acc1);
            ffma2(acc2, p1.x, xd[k], acc2);
            ffma2(acc3, p1.y, xd[k], acc3);
            ffma2(acc4, p2.x, xd[k], acc4);
            ffma2(acc5, p2.y, xd[k], acc5);
            ffma2(acc6, p3.x, xd[k], acc6);
            ffma2(acc7, p3.y, xd[k], acc7);
        }
        u64 accs[8] = {acc0, acc1, acc2, acc3, acc4, acc5, acc6, acc7};
#pragma unroll
        for (int j = 0; j < 8; j++) {
            float lo, hi; unpack2(lo, hi, accs[j]);
            ob[(size_t)(ch * 16 + 2 * j)     * NPIX] = __float2half_rn(lo);
            ob[(size_t)(ch * 16 + 2 * j + 1) * NPIX] = __float2half_rn(hi);
        }
    }
}

// ============================================================
// K2: depthwise 3x3, pad 1. Block = (b,ch,8-row tile), 256 threads.
// half2 loads; each thread computes a 2-col pair -> half2 stores.
// ============================================================
#define DWROWS 8
__global__ __launch_bounds__(256) void k_dw(const float* __restrict__ w) {
    const int tilesY = HH / DWROWS;                  // 32
    const int ytile = blockIdx.x & (tilesY - 1);
    const int ch    = (blockIdx.x / tilesY) % C3;
    const int b     = blockIdx.x / (tilesY * C3);
    const int tid   = threadIdx.x;

    const __half* in  = g_qkv + ((size_t)b * C3 + ch) * NPIX;
    __half*       out = g_dw  + ((size_t)b * C3 + ch) * NPIX;

    __shared__ float rows[DWROWS + 2][WW];
    const int y0 = ytile * DWROWS;
    for (int i = tid; i < (DWROWS + 2) * (WW / 2); i += 256) {
        int r = i / (WW / 2), c2 = i % (WW / 2);
        int y = y0 - 1 + r;
        float2 v = make_float2(0.f, 0.f);
        if (y >= 0 && y < HH)
            v = __half22float2(*(const __half2*)(in + y * WW + 2 * c2));
        rows[r][2 * c2] = v.x; rows[r][2 * c2 + 1] = v.y;
    }
    __syncthreads();

    const float w00 = w[ch*9+0], w01 = w[ch*9+1], w02 = w[ch*9+2];
    const float w10 = w[ch*9+3], w11 = w[ch*9+4], w12 = w[ch*9+5];
    const float w20 = w[ch*9+6], w21 = w[ch*9+7], w22 = w[ch*9+8];

    const int half = tid >> 7;           // 0/1 row interleave
    const int c2   = tid & 127;          // column pair index
    const int col0 = 2 * c2, col1 = col0 + 1;
    const float lm = (c2 > 0) ? 1.f : 0.f;
    const float rm = (c2 < 127) ? 1.f : 0.f;
    const int xl = max(col0 - 1, 0), xr = min(col1 + 1, WW - 1);

#pragma unroll
    for (int rr = 0; rr < DWROWS / 2; rr++) {
        const int r = 2 * rr + half;
        const float* r0 = rows[r], *r1 = rows[r + 1], *r2 = rows[r + 2];
        float a0 = r0[xl] * lm, b0 = r0[col0], c0v = r0[col1], d0 = r0[xr] * rm;
        float a1 = r1[xl] * lm, b1 = r1[col0], c1v = r1[col1], d1 = r1[xr] * rm;
        float a2 = r2[xl] * lm, b2 = r2[col0], c2v = r2[col1], d2 = r2[xr] * rm;
        float acc0 = w00*a0 + w01*b0 + w02*c0v + w10*a1 + w11*b1 + w12*c1v + w20*a2 + w21*b2 + w22*c2v;
        float acc1 = w00*b0 + w01*c0v + w02*d0 + w10*b1 + w11*c1v + w12*d1 + w20*b2 + w21*c2v + w22*d2;
        *(__half2*)(out + (y0 + r) * WW + col0) = __floats2half2_rn(acc0, acc1);
    }
}

// ============================================================
// K3: Gram G = Q K^T (48x48) + squared norms; FFMA2 over pixel pairs.
// ============================================================
#define TS2   32
#define CHUNK 1024
__global__ __launch_bounds__(256) void k_gram() {
    const int chunks = NPIX / CHUNK;  // 64
    const int b     = blockIdx.x / chunks;
    const int cbase = (blockIdx.x % chunks) * CHUNK;

    __shared__ float2 Qs[C][TS2 + 1], Ks[C][TS2 + 1];
    const int tid = threadIdx.x;
    const int c0 = (tid >> 4) * 3;
    const int d0 = (tid & 15) * 3;

    const __half* Q = g_dw + (size_t)b * C3 * NPIX;
    const __half* K = g_dw + (size_t)b * C3 * NPIX + (size_t)C * NPIX;

    u64 acc[3][3];
#pragma unroll
    for (int i = 0; i < 3; i++)
#pragma unroll
        for (int j = 0; j < 3; j++) acc[i][j] = 0ull;
    u64 sqa = 0ull;

    for (int sub = 0; sub < CHUNK / (2 * TS2); sub++) {
        const int tb = cbase + sub * (2 * TS2);
        for (int i = tid; i < C * TS2; i += 256) {
            int cc = i / TS2, t = i % TS2;
            Qs[cc][t] = __half22float2(*(const __half2*)(Q + (size_t)cc * NPIX + tb + 2 * t));
            Ks[cc][t] = __half22float2(*(const __half2*)(K + (size_t)cc * NPIX + tb + 2 * t));
        }
        __syncthreads();
#pragma unroll 4
        for (int t = 0; t < TS2; t++) {
            u64 q0 = *(const u64*)&Qs[c0][t];
            u64 q1 = *(const u64*)&Qs[c0 + 1][t];
            u64 q2 = *(const u64*)&Qs[c0 + 2][t];
            u64 k0 = *(const u64*)&Ks[d0][t];
            u64 k1 = *(const u64*)&Ks[d0 + 1][t];
            u64 k2 = *(const u64*)&Ks[d0 + 2][t];
            ffma2(acc[0][0], q0, k0, acc[0][0]); ffma2(acc[0][1], q0, k1, acc[0][1]); ffma2(acc[0][2], q0, k2, acc[0][2]);
            ffma2(acc[1][0], q1, k0, acc[1][0]); ffma2(acc[1][1], q1, k1, acc[1][1]); ffma2(acc[1][2], q1, k2, acc[1][2]);
            ffma2(acc[2][0], q2, k0, acc[2][0]); ffma2(acc[2][1], q2, k1, acc[2][1]); ffma2(acc[2][2], q2, k2, acc[2][2]);
            if (tid < C)          { u64 v = *(const u64*)&Qs[tid][t];     ffma2(sqa, v, v, sqa); }
            else if (tid < 2 * C) { u64 v = *(const u64*)&Ks[tid - C][t]; ffma2(sqa, v, v, sqa); }
        }
        __syncthreads();
    }

    float* gbase = g_small + b * (C * C + 2 * C);
#pragma unroll
    for (int i = 0; i < 3; i++)
#pragma unroll
        for (int j = 0; j < 3; j++) {
            float lo, hi; unpack2(lo, hi, acc[i][j]);
            atomicAdd(&gbase[(c0 + i) * C + (d0 + j)], lo + hi);
        }
    if (tid < 2 * C) { float lo, hi; unpack2(lo, hi, sqa); atomicAdd(&gbase[C * C + tid], lo + hi); }
}

// ============================================================
// K4 (fused attn+out): every block recomputes softmax + M = proj@attn
// from g_small (tiny), then out = M @ V with oc-packed FFMA2.
// ============================================================
__global__ __launch_bounds__(256, 2) void k_out(const float* __restrict__ proj,
                                                const float* __restrict__ temp,
                                                float* __restrict__ out) {
    __shared__ float A[C][C + 1];
    __shared__ float Psh[C * C];
    __shared__ float MT[C][C];      // MT[c][oc] = M[oc][c]
    __shared__ float qn[C], kn[C];
    const int tid = threadIdx.x, warp = tid >> 5, lane = tid & 31;
    const int b  = blockIdx.x >> 8;
    const int px = ((blockIdx.x & 255) << 8) | tid;
    const float* gbase = g_small + b * (C * C + 2 * C);
    const float T = temp[0];

    for (int i = tid; i < C * C; i += 256) Psh[i] = proj[i];
    if (tid < C)          qn[tid]     = fmaxf(sqrtf(gbase[C * C + tid]), 1e-12f);
    else if (tid < 2 * C) kn[tid - C] = fmaxf(sqrtf(gbase[C * C + tid]), 1e-12f);
    __syncthreads();

    for (int i = tid; i < C * C; i += 256) {
        int r = i / C, d = i % C;
        A[r][d] = gbase[i] * T / (qn[r] * kn[d]);
    }
    __syncthreads();

    // softmax: warp per row (8 warps -> 6 rows each)
    for (int r = warp; r < C; r += 8) {
        float v0 = A[r][lane];
        float v1 = (lane + 32 < C) ? A[r][lane + 32] : -1e30f;
        float mx = fmaxf(v0, v1);
#pragma unroll
        for (int o = 16; o > 0; o >>= 1) mx = fmaxf(mx, __shfl_xor_sync(~0u, mx, o));
        float e0 = expf(v0 - mx);
        float e1 = (lane + 32 < C) ? expf(v1 - mx) : 0.f;
        float s = e0 + e1;
#pragma unroll
        for (int o = 16; o > 0; o >>= 1) s += __shfl_xor_sync(~0u, s, o);
        float inv = 1.f / s;
        A[r][lane] = e0 * inv;
        if (lane + 32 < C) A[r][lane + 32] = e1 * inv;
    }
    __syncthreads();

    // MT[c][oc] = sum_d P[oc][d] * A[d][c]
    for (int i = tid; i < C * C; i += 256) {
        const int oc = i % C, cix = i / C;
        float a = 0.f;
#pragma unroll
        for (int d = 0; d < C; d++) a += Psh[oc * C + d] * A[d][cix];
        MT[cix][oc] = a;
    }

    // V pixel into duplicated packed registers
    const __half* vb = g_dw + (size_t)b * C3 * NPIX + (size_t)(2 * C) * NPIX + px;
    u64 vd[C];
#pragma unroll
    for (int cc = 0; cc < C; cc++) {
        float v = __half2float(vb[(size_t)cc * NPIX]);
        vd[cc] = pack2(v, v);
    }
    __syncthreads();

    float* ob = out + (size_t)b * C * NPIX + px;
    for (int ch = 0; ch < 3; ch++) {               // 16 oc per chunk
        u64 acc0 = 0, acc1 = 0, acc2 = 0, acc3 = 0, acc4 = 0, acc5 = 0, acc6 = 0, acc7 = 0;
#pragma unroll
        for (int cc = 0; cc < C; cc++) {
            const ulonglong2* m2 = (const ulonglong2*)&MT[cc][ch * 16];
            ulonglong2 p0 = m2[0], p1 = m2[1], p2 = m2[2], p3 = m2[3];
            ffma2(acc0, p0.x, vd[cc], acc0);
            ffma2(acc1, p0.y, vd[cc], acc1);
            ffma2(acc2, p1.x, vd[cc], acc2);
            ffma2(acc3, p1.y, vd[cc], acc3);
            ffma2(acc4, p2.x, vd[cc], acc4);
            ffma2(acc5, p2.y, vd[cc], acc5);
            ffma2(acc6, p3.x, vd[cc], acc6);
            ffma2(acc7, p3.y, vd[cc], acc7);
        }
        u64 accs[8] = {acc0, acc1, acc2, acc3, acc4, acc5, acc6, acc7};
#pragma unroll
        for (int j = 0; j < 8; j++) {
            float lo, hi; unpack2(lo, hi, accs[j]);
            ob[(size_t)(ch * 16 + 2 * j)     * NPIX] = lo;
            ob[(size_t)(ch * 16 + 2 * j + 1) * NPIX] = hi;
        }
    }
}

// ============================================================
extern "C" void kernel_launch(void* const* d_in, const int* in_sizes, int n_in,
                              void* d_out, int out_size) {
    const float* x      = (const float*)d_in[0];
    const float* qkv_w  = (const float*)d_in[1];
    const float* dw_w   = (const float*)d_in[2];
    const float* proj_w = (const float*)d_in[3];
    const float* temp   = (const float*)d_in[4];

    void* smallp = nullptr;
    cudaGetSymbolAddress(&smallp, g_small);
    cudaMemsetAsync(smallp, 0, sizeof(float) * Bc * (C * C + 2 * C));

    k_qkv <<<Bc * (NPIX / 256),       256>>>(x, qkv_w);
    k_dw  <<<Bc * C3 * (HH / DWROWS), 256>>>(dw_w);
    k_gram<<<Bc * (NPIX / CHUNK),     256>>>();
    k_out <<<Bc * (NPIX / 256),       256>>>(proj_w, temp, (float*)d_out);
}

// round 5
// speedup vs baseline: 1.1390x; 1.1390x over previous
#include <cuda_runtime.h>
#include <cuda_fp16.h>
#include <math.h>

#define Bc   4
#define C    48
#define C3   144
#define HH   256
#define WW   256
#define NPIX 65536   // HH*WW

typedef unsigned long long u64;

// packed f32x2 helpers (sm_100+: fma.rn.f32x2 = 2 fp32 FMAs / instruction)
__device__ __forceinline__ void ffma2(u64& d, u64 a, u64 b, u64 c) {
    asm("fma.rn.f32x2 %0, %1, %2, %3;" : "=l"(d) : "l"(a), "l"(b), "l"(c));
}
__device__ __forceinline__ u64 pack2(float x, float y) {
    u64 r; asm("mov.b64 %0, {%1, %2};" : "=l"(r) : "f"(x), "f"(y)); return r;
}
__device__ __forceinline__ void unpack2(float& x, float& y, u64 v) {
    asm("mov.b64 {%0, %1}, %2;" : "=f"(x), "=f"(y) : "l"(v));
}

// ---- scratch (device globals: no allocation allowed) ----
__device__ __half g_qkv[(size_t)Bc * C3 * NPIX];   // after 1x1 conv (75 MB)
__device__ __half g_dw [(size_t)Bc * C3 * NPIX];   // after depthwise (75 MB)
__device__ float  g_small[Bc * (C * C + 2 * C)];   // gram | qss | kss
__device__ float  g_M[Bc * C * C];                 // proj @ attn

// ============================================================
// K1: qkv 1x1 conv as tiled GEMM W[144,48] x X[48,128px].
// 288 threads = 18 oc-groups x 16 px-groups; 8 oc x 8 px per thread.
// k chunked by 24; both operands staged in smem; FFMA2 over px pairs.
// ============================================================
__global__ void __launch_bounds__(288, 2) k_qkv(const float* __restrict__ x,
                                                const float* __restrict__ w) {
    __shared__ float Ws[24][C3];     // 13.8 KB
    __shared__ u64   Xs[24][64];     // px-pairs, 12.3 KB
    const int tid = threadIdx.x;
    const int b   = blockIdx.x >> 9;            // 512 px-tiles / batch
    const int px0 = (blockIdx.x & 511) << 7;    // 128 px / block
    const int og  = tid / 16;                   // 0..17
    const int pg  = tid & 15;                   // 0..15
    const int oc0 = og * 8;
    const int xb4 = pg * 4;                     // u64 index into Xs row

    const float* xb = x + (size_t)b * C * NPIX + px0;

    u64 acc[8][4];
#pragma unroll
    for (int o = 0; o < 8; o++)
#pragma unroll
        for (int j = 0; j < 4; j++) acc[o][j] = 0ull;

#pragma unroll 1
    for (int kc = 0; kc < C; kc += 24) {
        __syncthreads();
        for (int i = tid; i < 24 * C3; i += 288) {
            int kk = i / C3, oc = i % C3;
            Ws[kk][oc] = w[oc * C + kc + kk];
        }
        for (int i = tid; i < 24 * 32; i += 288) {
            int kk = i >> 5, q = i & 31;
            float4 v = *(const float4*)(xb + (size_t)(kc + kk) * NPIX + (q << 2));
            *(float4*)&Xs[kk][q * 2] = v;
        }
        __syncthreads();
#pragma unroll
        for (int kk = 0; kk < 24; kk++) {
            float ws[8];
            *(float4*)&ws[0] = *(const float4*)&Ws[kk][oc0];
            *(float4*)&ws[4] = *(const float4*)&Ws[kk][oc0 + 4];
            u64 xv[4];
            *(uint4*)&xv[0] = *(const uint4*)&Xs[kk][xb4];
            *(uint4*)&xv[2] = *(const uint4*)&Xs[kk][xb4 + 2];
#pragma unroll
            for (int o = 0; o < 8; o++) {
                u64 wd = pack2(ws[o], ws[o]);
#pragma unroll
                for (int j = 0; j < 4; j++) ffma2(acc[o][j], wd, xv[j], acc[o][j]);
            }
        }
    }

    __half* ob = g_qkv + (size_t)b * C3 * NPIX + px0 + pg * 8;
#pragma unroll
    for (int o = 0; o < 8; o++) {
        __half2 h[4];
#pragma unroll
        for (int j = 0; j < 4; j++) {
            float lo, hi; unpack2(lo, hi, acc[o][j]);
            h[j] = __floats2half2_rn(lo, hi);
        }
        *(uint4*)(ob + (size_t)(oc0 + o) * NPIX) = *(uint4*)h;
    }
}

// ============================================================
// K2: depthwise 3x3, pad 1. Block = (b,ch,8-row tile), 256 threads.
// ============================================================
#define DWROWS 8
__global__ __launch_bounds__(256) void k_dw(const float* __restrict__ w) {
    const int tilesY = HH / DWROWS;
    const int ytile = blockIdx.x & (tilesY - 1);
    const int ch    = (blockIdx.x / tilesY) % C3;
    const int b     = blockIdx.x / (tilesY * C3);
    const int tid   = threadIdx.x;

    const __half* in  = g_qkv + ((size_t)b * C3 + ch) * NPIX;
    __half*       out = g_dw  + ((size_t)b * C3 + ch) * NPIX;

    __shared__ float rows[DWROWS + 2][WW];
    const int y0 = ytile * DWROWS;
    for (int i = tid; i < (DWROWS + 2) * (WW / 2); i += 256) {
        int r = i / (WW / 2), c2 = i % (WW / 2);
        int y = y0 - 1 + r;
        float2 v = make_float2(0.f, 0.f);
        if (y >= 0 && y < HH)
            v = __half22float2(*(const __half2*)(in + y * WW + 2 * c2));
        rows[r][2 * c2] = v.x; rows[r][2 * c2 + 1] = v.y;
    }
    __syncthreads();

    const float w00 = w[ch*9+0], w01 = w[ch*9+1], w02 = w[ch*9+2];
    const float w10 = w[ch*9+3], w11 = w[ch*9+4], w12 = w[ch*9+5];
    const float w20 = w[ch*9+6], w21 = w[ch*9+7], w22 = w[ch*9+8];

    const int half = tid >> 7;
    const int c2   = tid & 127;
    const int col0 = 2 * c2, col1 = col0 + 1;
    const float lm = (c2 > 0) ? 1.f : 0.f;
    const float rm = (c2 < 127) ? 1.f : 0.f;
    const int xl = max(col0 - 1, 0), xr = min(col1 + 1, WW - 1);

#pragma unroll
    for (int rr = 0; rr < DWROWS / 2; rr++) {
        const int r = 2 * rr + half;
        const float* r0 = rows[r], *r1 = rows[r + 1], *r2 = rows[r + 2];
        float a0 = r0[xl] * lm, b0 = r0[col0], c0v = r0[col1], d0 = r0[xr] * rm;
        float a1 = r1[xl] * lm, b1 = r1[col0], c1v = r1[col1], d1 = r1[xr] * rm;
        float a2 = r2[xl] * lm, b2 = r2[col0], c2v = r2[col1], d2 = r2[xr] * rm;
        float acc0 = w00*a0 + w01*b0 + w02*c0v + w10*a1 + w11*b1 + w12*c1v + w20*a2 + w21*b2 + w22*c2v;
        float acc1 = w00*b0 + w01*c0v + w02*d0 + w10*b1 + w11*c1v + w12*d1 + w20*b2 + w21*c2v + w22*d2;
        *(__half2*)(out + (y0 + r) * WW + col0) = __floats2half2_rn(acc0, acc1);
    }
}

// ============================================================
// K3: Gram G = Q K^T (48x48) + squared norms; FFMA2 over px pairs.
// ============================================================
#define TS2   32
#define CHUNK 1024
__global__ __launch_bounds__(256) void k_gram() {
    const int chunks = NPIX / CHUNK;
    const int b     = blockIdx.x / chunks;
    const int cbase = (blockIdx.x % chunks) * CHUNK;

    __shared__ float2 Qs[C][TS2 + 1], Ks[C][TS2 + 1];
    const int tid = threadIdx.x;
    const int c0 = (tid >> 4) * 3;
    const int d0 = (tid & 15) * 3;

    const __half* Q = g_dw + (size_t)b * C3 * NPIX;
    const __half* K = g_dw + (size_t)b * C3 * NPIX + (size_t)C * NPIX;

    u64 acc[3][3];
#pragma unroll
    for (int i = 0; i < 3; i++)
#pragma unroll
        for (int j = 0; j < 3; j++) acc[i][j] = 0ull;
    u64 sqa = 0ull;

    for (int sub = 0; sub < CHUNK / (2 * TS2); sub++) {
        const int tb = cbase + sub * (2 * TS2);
        for (int i = tid; i < C * TS2; i += 256) {
            int cc = i / TS2, t = i % TS2;
            Qs[cc][t] = __half22float2(*(const __half2*)(Q + (size_t)cc * NPIX + tb + 2 * t));
            Ks[cc][t] = __half22float2(*(const __half2*)(K + (size_t)cc * NPIX + tb + 2 * t));
        }
        __syncthreads();
#pragma unroll 4
        for (int t = 0; t < TS2; t++) {
            u64 q0 = *(const u64*)&Qs[c0][t];
            u64 q1 = *(const u64*)&Qs[c0 + 1][t];
            u64 q2 = *(const u64*)&Qs[c0 + 2][t];
            u64 k0 = *(const u64*)&Ks[d0][t];
            u64 k1 = *(const u64*)&Ks[d0 + 1][t];
            u64 k2 = *(const u64*)&Ks[d0 + 2][t];
            ffma2(acc[0][0], q0, k0, acc[0][0]); ffma2(acc[0][1], q0, k1, acc[0][1]); ffma2(acc[0][2], q0, k2, acc[0][2]);
            ffma2(acc[1][0], q1, k0, acc[1][0]); ffma2(acc[1][1], q1, k1, acc[1][1]); ffma2(acc[1][2], q1, k2, acc[1][2]);
            ffma2(acc[2][0], q2, k0, acc[2][0]); ffma2(acc[2][1], q2, k1, acc[2][1]); ffma2(acc[2][2], q2, k2, acc[2][2]);
            if (tid < C)          { u64 v = *(const u64*)&Qs[tid][t];     ffma2(sqa, v, v, sqa); }
            else if (tid < 2 * C) { u64 v = *(const u64*)&Ks[tid - C][t]; ffma2(sqa, v, v, sqa); }
        }
        __syncthreads();
    }

    float* gbase = g_small + b * (C * C + 2 * C);
#pragma unroll
    for (int i = 0; i < 3; i++)
#pragma unroll
        for (int j = 0; j < 3; j++) {
            float lo, hi; unpack2(lo, hi, acc[i][j]);
            atomicAdd(&gbase[(c0 + i) * C + (d0 + j)], lo + hi);
        }
    if (tid < 2 * C) { float lo, hi; unpack2(lo, hi, sqa); atomicAdd(&gbase[C * C + tid], lo + hi); }
}

// ============================================================
// K4: softmax(G/(qn*kn)*T) then M = proj @ attn -> g_M. 4 blocks.
// ============================================================
__global__ __launch_bounds__(256) void k_attn(const float* __restrict__ proj,
                                              const float* __restrict__ temp) {
    const int b = blockIdx.x;
    const int tid = threadIdx.x;
    const int warp = tid >> 5, lane = tid & 31;
    __shared__ float A[C][C + 1];
    __shared__ float P[C * C];
    __shared__ float qn[C], kn[C];
    const float* gbase = g_small + b * (C * C + 2 * C);
    const float T = temp[0];

    for (int i = tid; i < C * C; i += 256) P[i] = proj[i];
    if (tid < C)          qn[tid]     = fmaxf(sqrtf(gbase[C * C + tid]), 1e-12f);
    else if (tid < 2 * C) kn[tid - C] = fmaxf(sqrtf(gbase[C * C + tid]), 1e-12f);
    __syncthreads();

    for (int i = tid; i < C * C; i += 256) {
        int r = i / C, d = i % C;
        A[r][d] = gbase[i] * T / (qn[r] * kn[d]);
    }
    __syncthreads();

    for (int r = warp; r < C; r += 8) {
        float v0 = A[r][lane];
        float v1 = (lane + 32 < C) ? A[r][lane + 32] : -1e30f;
        float mx = fmaxf(v0, v1);
#pragma unroll
        for (int o = 16; o > 0; o >>= 1) mx = fmaxf(mx, __shfl_xor_sync(~0u, mx, o));
        float e0 = expf(v0 - mx);
        float e1 = (lane + 32 < C) ? expf(v1 - mx) : 0.f;
        float s = e0 + e1;
#pragma unroll
        for (int o = 16; o > 0; o >>= 1) s += __shfl_xor_sync(~0u, s, o);
        float inv = 1.f / s;
        A[r][lane] = e0 * inv;
        if (lane + 32 < C) A[r][lane + 32] = e1 * inv;
    }
    __syncthreads();

    for (int i = tid; i < C * C; i += 256) {
        const int oc = i / C, d = i % C;
        float a = 0.f;
#pragma unroll
        for (int cc = 0; cc < C; cc++) a += P[oc * C + cc] * A[cc][d];
        g_M[b * C * C + i] = a;
    }
}

// ============================================================
// K5: out = M @ V as tiled GEMM M[48,48] x V[48,256px].
// 192 threads = 6 oc-groups x 32 px-groups; 8 oc x 8 px per thread.
// ============================================================
__global__ void __launch_bounds__(192, 2) k_out(float* __restrict__ out) {
    __shared__ float Ms[24][C];     // Ms[c][oc] = M[oc][c], 4.6 KB
    __shared__ u64   Xs[24][128];   // V px-pairs fp32, 24.6 KB
    const int tid = threadIdx.x;
    const int b   = blockIdx.x >> 8;            // 256 px-tiles / batch
    const int px0 = (blockIdx.x & 255) << 8;    // 256 px / block
    const int og  = tid >> 5;                   // 0..5
    const int pg  = tid & 31;                   // 0..31
    const int oc0 = og * 8;
    const int xb4 = pg * 4;

    const __half* vb = g_dw + (size_t)b * C3 * NPIX + (size_t)(2 * C) * NPIX + px0;
    const float*  Mb = g_M + b * C * C;

    u64 acc[8][4];
#pragma unroll
    for (int o = 0; o < 8; o++)
#pragma unroll
        for (int j = 0; j < 4; j++) acc[o][j] = 0ull;

#pragma unroll 1
    for (int kc = 0; kc < C; kc += 24) {
        __syncthreads();
        for (int i = tid; i < 24 * C; i += 192) {
            int kk = i / C, oc = i % C;
            Ms[kk][oc] = Mb[oc * C + kc + kk];
        }
        for (int i = tid; i < 24 * 64; i += 192) {
            int kk = i >> 6, q = i & 63;
            uint2 raw = *(const uint2*)(vb + (size_t)(kc + kk) * NPIX + (q << 2));
            float2 f01 = __half22float2(*(__half2*)&raw.x);
            float2 f23 = __half22float2(*(__half2*)&raw.y);
            *(float4*)&Xs[kk][q * 2] = make_float4(f01.x, f01.y, f23.x, f23.y);
        }
        __syncthreads();
#pragma unroll
        for (int kk = 0; kk < 24; kk++) {
            float ms[8];
            *(float4*)&ms[0] = *(const float4*)&Ms[kk][oc0];
            *(float4*)&ms[4] = *(const float4*)&Ms[kk][oc0 + 4];
            u64 xv[4];
            *(uint4*)&xv[0] = *(const uint4*)&Xs[kk][xb4];
            *(uint4*)&xv[2] = *(const uint4*)&Xs[kk][xb4 + 2];
#pragma unroll
            for (int o = 0; o < 8; o++) {
                u64 md = pack2(ms[o], ms[o]);
#pragma unroll
                for (int j = 0; j < 4; j++) ffma2(acc[o][j], md, xv[j], acc[o][j]);
            }
        }
    }

    float* ob = out + (size_t)b * C * NPIX + px0 + pg * 8;
#pragma unroll
    for (int o = 0; o < 8; o++) {
        *(uint4*)(ob + (size_t)(oc0 + o) * NPIX)     = *(uint4*)&acc[o][0];
        *(uint4*)(ob + (size_t)(oc0 + o) * NPIX + 4) = *(uint4*)&acc[o][2];
    }
}

// ============================================================
extern "C" void kernel_launch(void* const* d_in, const int* in_sizes, int n_in,
                              void* d_out, int out_size) {
    const float* x      = (const float*)d_in[0];
    const float* qkv_w  = (const float*)d_in[1];
    const float* dw_w   = (const float*)d_in[2];
    const float* proj_w = (const float*)d_in[3];
    const float* temp   = (const float*)d_in[4];

    void* smallp = nullptr;
    cudaGetSymbolAddress(&smallp, g_small);
    cudaMemsetAsync(smallp, 0, sizeof(float) * Bc * (C * C + 2 * C));

    k_qkv <<<Bc * 512,                288>>>(x, qkv_w);
    k_dw  <<<Bc * C3 * (HH / DWROWS), 256>>>(dw_w);
    k_gram<<<Bc * (NPIX / CHUNK),     256>>>();
    k_attn<<<Bc,                      256>>>(proj_w, temp);
    k_out <<<Bc * 256,                192>>>((float*)d_out);
}